// round 5
// baseline (speedup 1.0000x reference)
#include <cuda_runtime.h>
#include <cuda_bf16.h>
#include <cstdint>

// Problem constants (fixed by the dataset)
#define NNODES 100000
#define EMAX   1600000
#define INC    128
#define OUTC   128

typedef unsigned long long ull;

// Scratch: device globals (no allocation allowed)
__device__ float g_sum[(size_t)NNODES * INC];  // mean-aggregated features
__device__ int   g_cnt[NNODES];                // in-degree
__device__ int   g_off[NNODES];                // CSR row offsets (exclusive scan)
__device__ int   g_cursor[NNODES];             // fill cursors
__device__ int   g_csrc[EMAX];                 // CSR src indices grouped by dst

// Packed dual-fp32 FMA (Blackwell f32x2 path; 2x fp32 FMA throughput)
#define FMA_F32X2(d, a, b) \
    asm("fma.rn.f32x2 %0, %1, %2, %0;" : "+l"(d) : "l"(a), "l"(b))

// ---------------------------------------------------------------------------
// Kernel 1: zero degree counters
// ---------------------------------------------------------------------------
__global__ void zero_cnt() {
    int idx = blockIdx.x * blockDim.x + threadIdx.x;
    if (idx < NNODES) g_cnt[idx] = 0;
}

// ---------------------------------------------------------------------------
// Kernel 2: count in-degrees
// ---------------------------------------------------------------------------
__global__ void count_deg(const int* __restrict__ edge_row, int E) {
    int e = blockIdx.x * blockDim.x + threadIdx.x;
    if (e < E) atomicAdd(&g_cnt[edge_row[e]], 1);
}

// ---------------------------------------------------------------------------
// Kernel 3: single-block exclusive scan of g_cnt -> g_off (and g_cursor copy)
// ---------------------------------------------------------------------------
__global__ void scan_offsets() {
    __shared__ int sums[1024];
    int t = threadIdx.x;
    const int CH = (NNODES + 1023) / 1024;   // 98
    int begin = t * CH;
    int end   = begin + CH; if (end > NNODES) end = NNODES;

    int s = 0;
    for (int i = begin; i < end; i++) s += g_cnt[i];
    sums[t] = s;
    __syncthreads();

    // Hillis-Steele inclusive scan (race-safe: read, sync, write, sync)
    for (int off = 1; off < 1024; off <<= 1) {
        int v = (t >= off) ? sums[t - off] : 0;
        __syncthreads();
        sums[t] += v;
        __syncthreads();
    }
    int run = (t == 0) ? 0 : sums[t - 1];   // exclusive prefix for this chunk

    for (int i = begin; i < end; i++) {
        g_off[i]    = run;
        g_cursor[i] = run;
        run += g_cnt[i];
    }
}

// ---------------------------------------------------------------------------
// Kernel 4: fill CSR buckets
// ---------------------------------------------------------------------------
__global__ void fill_csr(const int* __restrict__ edge_row,
                         const int* __restrict__ edge_col, int E) {
    int e = blockIdx.x * blockDim.x + threadIdx.x;
    if (e >= E) return;
    int dst = edge_row[e];
    int src = edge_col[e];
    int pos = atomicAdd(&g_cursor[dst], 1);
    g_csrc[pos] = src;
}

// ---------------------------------------------------------------------------
// Kernel 5: gather aggregation (mean). One warp per node; lane = one float4.
// ---------------------------------------------------------------------------
__global__ __launch_bounds__(256)
void aggregate(const float* __restrict__ x) {
    int tid  = blockIdx.x * blockDim.x + threadIdx.x;
    int node = tid >> 5;
    int lane = tid & 31;
    if (node >= NNODES) return;

    int start = g_off[node];
    int deg   = g_cnt[node];
    const float4* x4 = reinterpret_cast<const float4*>(x);

    float4 a0 = make_float4(0.f, 0.f, 0.f, 0.f);
    float4 a1 = a0, a2 = a0, a3 = a0;

    int i = 0;
    for (; i + 4 <= deg; i += 4) {
        int s0 = g_csrc[start + i + 0];
        int s1 = g_csrc[start + i + 1];
        int s2 = g_csrc[start + i + 2];
        int s3 = g_csrc[start + i + 3];
        float4 v0 = x4[(size_t)s0 * 32 + lane];
        float4 v1 = x4[(size_t)s1 * 32 + lane];
        float4 v2 = x4[(size_t)s2 * 32 + lane];
        float4 v3 = x4[(size_t)s3 * 32 + lane];
        a0.x += v0.x; a0.y += v0.y; a0.z += v0.z; a0.w += v0.w;
        a1.x += v1.x; a1.y += v1.y; a1.z += v1.z; a1.w += v1.w;
        a2.x += v2.x; a2.y += v2.y; a2.z += v2.z; a2.w += v2.w;
        a3.x += v3.x; a3.y += v3.y; a3.z += v3.z; a3.w += v3.w;
    }
    for (; i < deg; i++) {
        int s = g_csrc[start + i];
        float4 v = x4[(size_t)s * 32 + lane];
        a0.x += v.x; a0.y += v.y; a0.z += v.z; a0.w += v.w;
    }

    float inv = 1.0f / fmaxf((float)deg, 1.0f);
    float4 r;
    r.x = (a0.x + a1.x + a2.x + a3.x) * inv;
    r.y = (a0.y + a1.y + a2.y + a3.y) * inv;
    r.z = (a0.z + a1.z + a2.z + a3.z) * inv;
    r.w = (a0.w + a1.w + a2.w + a3.w) * inv;

    reinterpret_cast<float4*>(g_sum)[(size_t)node * 32 + lane] = r;
}

// ---------------------------------------------------------------------------
// Kernel 6: fused GEMM:  out = relu( [agg | x] @ [W_l ; W_r] + b_l )
// Tile 128x128 per block, 256 threads, 8x8 micro-tile per thread, f32x2 FMA.
// ---------------------------------------------------------------------------
#define KC 32
#define ASTRIDE 33  // float2 units, padded

__global__ __launch_bounds__(256, 2)
void fused_gemm(const float* __restrict__ x,
                const float* __restrict__ Wl,
                const float* __restrict__ bl,
                const float* __restrict__ Wr,
                float* __restrict__ out,
                int Nn) {
    __shared__ float2 As2[128 * ASTRIDE];   // [row][kk] duplicated (a,a)
    __shared__ float  Bs[KC * 128];         // [kk][col]

    int t  = threadIdx.x;
    int tx = t & 15;        // column pair group
    int ty = t >> 4;        // row group
    int row_base = blockIdx.x * 128;

    ull acc[8][4];
#pragma unroll
    for (int i = 0; i < 8; i++)
#pragma unroll
        for (int j = 0; j < 4; j++) acc[i][j] = 0ull;

    for (int chunk = 0; chunk < 256 / KC; chunk++) {
        int k0 = chunk * KC;

        // ---- Load A tile: 128 rows x KC floats = 1024 float4, 4 per thread
#pragma unroll
        for (int i = 0; i < 4; i++) {
            int idx = t + 256 * i;        // float4 index
            int row = idx >> 3;           // 8 float4 per row (KC=32)
            int f4  = idx & 7;
            int rg  = row_base + row;
            float4 v = make_float4(0.f, 0.f, 0.f, 0.f);
            if (rg < Nn) {
                if (k0 < 128)
                    v = *reinterpret_cast<const float4*>(
                        g_sum + (size_t)rg * INC + k0 + f4 * 4);
                else
                    v = *reinterpret_cast<const float4*>(
                        x + (size_t)rg * INC + (k0 - 128) + f4 * 4);
            }
            float2* dst = &As2[row * ASTRIDE + f4 * 4];
            dst[0] = make_float2(v.x, v.x);
            dst[1] = make_float2(v.y, v.y);
            dst[2] = make_float2(v.z, v.z);
            dst[3] = make_float2(v.w, v.w);
        }

        // ---- Load B tile: KC x 128 floats = 1024 float4, 4 per thread
#pragma unroll
        for (int i = 0; i < 4; i++) {
            int idx  = t + 256 * i;
            int kk   = idx >> 5;
            int c4   = idx & 31;
            int kg   = k0 + kk;
            float4 v;
            if (kg < 128) v = *reinterpret_cast<const float4*>(Wl + kg * OUTC + c4 * 4);
            else          v = *reinterpret_cast<const float4*>(Wr + (kg - 128) * OUTC + c4 * 4);
            *reinterpret_cast<float4*>(&Bs[kk * 128 + c4 * 4]) = v;
        }
        __syncthreads();

        // ---- Compute
#pragma unroll 4
        for (int kk = 0; kk < KC; kk++) {
            ull a2[8], b2[4];
#pragma unroll
            for (int i = 0; i < 8; i++)
                a2[i] = *reinterpret_cast<const ull*>(&As2[(ty + 16 * i) * ASTRIDE + kk]);
#pragma unroll
            for (int j = 0; j < 4; j++)
                b2[j] = *reinterpret_cast<const ull*>(&Bs[kk * 128 + tx * 2 + 32 * j]);
#pragma unroll
            for (int i = 0; i < 8; i++)
#pragma unroll
                for (int j = 0; j < 4; j++)
                    FMA_F32X2(acc[i][j], a2[i], b2[j]);
        }
        __syncthreads();
    }

    // ---- Epilogue: bias + relu + store
    float2 bias[4];
#pragma unroll
    for (int j = 0; j < 4; j++)
        bias[j] = *reinterpret_cast<const float2*>(bl + tx * 2 + 32 * j);

#pragma unroll
    for (int i = 0; i < 8; i++) {
        int r = row_base + ty + 16 * i;
        if (r < Nn) {
#pragma unroll
            for (int j = 0; j < 4; j++) {
                float2 v = *reinterpret_cast<float2*>(&acc[i][j]);
                float2 o;
                o.x = fmaxf(v.x + bias[j].x, 0.0f);
                o.y = fmaxf(v.y + bias[j].y, 0.0f);
                *reinterpret_cast<float2*>(out + (size_t)r * OUTC + tx * 2 + 32 * j) = o;
            }
        }
    }
}

// ---------------------------------------------------------------------------
// Launch
// ---------------------------------------------------------------------------
extern "C" void kernel_launch(void* const* d_in, const int* in_sizes, int n_in,
                              void* d_out, int out_size) {
    const float* x        = (const float*)d_in[0];
    const int*   edge_row = (const int*)d_in[1];
    const int*   edge_col = (const int*)d_in[2];
    const float* Wl       = (const float*)d_in[3];
    const float* bl       = (const float*)d_in[4];
    const float* Wr       = (const float*)d_in[5];
    float*       out      = (float*)d_out;

    int E = in_sizes[1];

    // 1) CSR build
    zero_cnt<<<(NNODES + 255) / 256, 256>>>();
    count_deg<<<(E + 255) / 256, 256>>>(edge_row, E);
    scan_offsets<<<1, 1024>>>();
    fill_csr<<<(E + 255) / 256, 256>>>(edge_row, edge_col, E);

    // 2) gather aggregation (warp per node)
    {
        long long threads = (long long)NNODES * 32;
        int blocks = (int)((threads + 255) / 256);
        aggregate<<<blocks, 256>>>(x);
    }

    // 3) fused dual GEMM + bias + relu
    {
        int blocks = (NNODES + 127) / 128;
        fused_gemm<<<blocks, 256>>>(x, Wl, bl, Wr, out, NNODES);
    }
}

// round 6
// speedup vs baseline: 1.1480x; 1.1480x over previous
#include <cuda_runtime.h>
#include <cuda_bf16.h>
#include <cstdint>

// Problem constants (fixed by the dataset)
#define NNODES 100000
#define INC    128
#define OUTC   128

typedef unsigned long long ull;

// Scratch: device globals (no allocation allowed)
__device__ float g_sum[(size_t)NNODES * INC];   // segment sums (un-normalized)
__device__ float g_deg[NNODES];                 // degree counts (float)

// Packed dual-fp32 FMA (Blackwell f32x2 path; 2x fp32 FMA throughput)
#define FMA_F32X2(d, a, b) \
    asm("fma.rn.f32x2 %0, %1, %2, %0;" : "+l"(d) : "l"(a), "l"(b))

// ---------------------------------------------------------------------------
// Kernel 1: zero scratch (vectorized float4)
// ---------------------------------------------------------------------------
__global__ void zero_scratch() {
    int idx = blockIdx.x * blockDim.x + threadIdx.x;
    const int NSUM4 = NNODES * INC / 4;          // 3.2M float4
    if (idx < NSUM4)
        reinterpret_cast<float4*>(g_sum)[idx] = make_float4(0.f, 0.f, 0.f, 0.f);
    if (idx < NNODES)
        g_deg[idx] = 0.0f;
}

// ---------------------------------------------------------------------------
// Kernel 2: edge scatter. One warp per edge; each lane reduces one float4.
// ---------------------------------------------------------------------------
__global__ void edge_scatter(const float* __restrict__ x,
                             const int* __restrict__ edge_row,
                             const int* __restrict__ edge_col,
                             int E) {
    int tid  = blockIdx.x * blockDim.x + threadIdx.x;
    int e    = tid >> 5;
    int lane = tid & 31;
    if (e >= E) return;

    int dst = edge_row[e];
    int src = edge_col[e];

    const float4* xs = reinterpret_cast<const float4*>(x + (size_t)src * INC);
    float4 v = xs[lane];

    float4* d = reinterpret_cast<float4*>(g_sum + (size_t)dst * INC) + lane;
    asm volatile("red.global.add.v4.f32 [%0], {%1, %2, %3, %4};"
                 :: "l"(d), "f"(v.x), "f"(v.y), "f"(v.z), "f"(v.w)
                 : "memory");

    if (lane == 0) atomicAdd(&g_deg[dst], 1.0f);
}

// ---------------------------------------------------------------------------
// GEMM tile machinery: 128x128 tile, 256 threads, 8x8 micro-tile, f32x2 FMA.
// K = 128 (4 chunks of KC=32).
// ---------------------------------------------------------------------------
#define KC 32
#define ASTRIDE 33  // float2 units, padded

// GEMM1: out = x @ W_r + b    (independent of aggregation; overlapped)
__global__ __launch_bounds__(256, 2)
void gemm_xr(const float* __restrict__ x,
             const float* __restrict__ Wr,
             const float* __restrict__ bl,
             float* __restrict__ out,
             int Nn) {
    __shared__ float2 As2[128 * ASTRIDE];
    __shared__ float  Bs[KC * 128];

    int t  = threadIdx.x;
    int tx = t & 15;
    int ty = t >> 4;
    int row_base = blockIdx.x * 128;

    ull acc[8][4];
#pragma unroll
    for (int i = 0; i < 8; i++)
#pragma unroll
        for (int j = 0; j < 4; j++) acc[i][j] = 0ull;

    for (int chunk = 0; chunk < 128 / KC; chunk++) {
        int k0 = chunk * KC;

#pragma unroll
        for (int i = 0; i < 4; i++) {
            int idx = t + 256 * i;
            int row = idx >> 3;
            int f4  = idx & 7;
            int rg  = row_base + row;
            float4 v = make_float4(0.f, 0.f, 0.f, 0.f);
            if (rg < Nn)
                v = *reinterpret_cast<const float4*>(x + (size_t)rg * INC + k0 + f4 * 4);
            float2* dst = &As2[row * ASTRIDE + f4 * 4];
            dst[0] = make_float2(v.x, v.x);
            dst[1] = make_float2(v.y, v.y);
            dst[2] = make_float2(v.z, v.z);
            dst[3] = make_float2(v.w, v.w);
        }
#pragma unroll
        for (int i = 0; i < 4; i++) {
            int idx = t + 256 * i;
            int kk  = idx >> 5;
            int c4  = idx & 31;
            float4 v = *reinterpret_cast<const float4*>(Wr + (k0 + kk) * OUTC + c4 * 4);
            *reinterpret_cast<float4*>(&Bs[kk * 128 + c4 * 4]) = v;
        }
        __syncthreads();

#pragma unroll 4
        for (int kk = 0; kk < KC; kk++) {
            ull a2[8], b2[4];
#pragma unroll
            for (int i = 0; i < 8; i++)
                a2[i] = *reinterpret_cast<const ull*>(&As2[(ty + 16 * i) * ASTRIDE + kk]);
#pragma unroll
            for (int j = 0; j < 4; j++)
                b2[j] = *reinterpret_cast<const ull*>(&Bs[kk * 128 + tx * 2 + 32 * j]);
#pragma unroll
            for (int i = 0; i < 8; i++)
#pragma unroll
                for (int j = 0; j < 4; j++)
                    FMA_F32X2(acc[i][j], a2[i], b2[j]);
        }
        __syncthreads();
    }

    float2 bias[4];
#pragma unroll
    for (int j = 0; j < 4; j++)
        bias[j] = *reinterpret_cast<const float2*>(bl + tx * 2 + 32 * j);

#pragma unroll
    for (int i = 0; i < 8; i++) {
        int r = row_base + ty + 16 * i;
        if (r < Nn) {
#pragma unroll
            for (int j = 0; j < 4; j++) {
                float2 v = *reinterpret_cast<float2*>(&acc[i][j]);
                float2 o;
                o.x = v.x + bias[j].x;
                o.y = v.y + bias[j].y;
                *reinterpret_cast<float2*>(out + (size_t)r * OUTC + tx * 2 + 32 * j) = o;
            }
        }
    }
}

// GEMM2: out = relu( (g_sum * 1/deg) @ W_l + out )   (after scatter joins)
__global__ __launch_bounds__(256, 2)
void gemm_aggl(const float* __restrict__ Wl,
               float* __restrict__ out,
               int Nn) {
    __shared__ float2 As2[128 * ASTRIDE];
    __shared__ float  Bs[KC * 128];
    __shared__ float  rdeg[128];

    int t  = threadIdx.x;
    int tx = t & 15;
    int ty = t >> 4;
    int row_base = blockIdx.x * 128;

    if (t < 128) {
        int r = row_base + t;
        rdeg[t] = (r < Nn) ? (1.0f / fmaxf(g_deg[r], 1.0f)) : 0.0f;
    }
    __syncthreads();

    ull acc[8][4];
#pragma unroll
    for (int i = 0; i < 8; i++)
#pragma unroll
        for (int j = 0; j < 4; j++) acc[i][j] = 0ull;

    for (int chunk = 0; chunk < 128 / KC; chunk++) {
        int k0 = chunk * KC;

#pragma unroll
        for (int i = 0; i < 4; i++) {
            int idx = t + 256 * i;
            int row = idx >> 3;
            int f4  = idx & 7;
            int rg  = row_base + row;
            float4 v = make_float4(0.f, 0.f, 0.f, 0.f);
            if (rg < Nn) {
                v = *reinterpret_cast<const float4*>(g_sum + (size_t)rg * INC + k0 + f4 * 4);
                float s = rdeg[row];
                v.x *= s; v.y *= s; v.z *= s; v.w *= s;
            }
            float2* dst = &As2[row * ASTRIDE + f4 * 4];
            dst[0] = make_float2(v.x, v.x);
            dst[1] = make_float2(v.y, v.y);
            dst[2] = make_float2(v.z, v.z);
            dst[3] = make_float2(v.w, v.w);
        }
#pragma unroll
        for (int i = 0; i < 4; i++) {
            int idx = t + 256 * i;
            int kk  = idx >> 5;
            int c4  = idx & 31;
            float4 v = *reinterpret_cast<const float4*>(Wl + (k0 + kk) * OUTC + c4 * 4);
            *reinterpret_cast<float4*>(&Bs[kk * 128 + c4 * 4]) = v;
        }
        __syncthreads();

#pragma unroll 4
        for (int kk = 0; kk < KC; kk++) {
            ull a2[8], b2[4];
#pragma unroll
            for (int i = 0; i < 8; i++)
                a2[i] = *reinterpret_cast<const ull*>(&As2[(ty + 16 * i) * ASTRIDE + kk]);
#pragma unroll
            for (int j = 0; j < 4; j++)
                b2[j] = *reinterpret_cast<const ull*>(&Bs[kk * 128 + tx * 2 + 32 * j]);
#pragma unroll
            for (int i = 0; i < 8; i++)
#pragma unroll
                for (int j = 0; j < 4; j++)
                    FMA_F32X2(acc[i][j], a2[i], b2[j]);
        }
        __syncthreads();
    }

#pragma unroll
    for (int i = 0; i < 8; i++) {
        int r = row_base + ty + 16 * i;
        if (r < Nn) {
#pragma unroll
            for (int j = 0; j < 4; j++) {
                float* op = out + (size_t)r * OUTC + tx * 2 + 32 * j;
                float2 prev = *reinterpret_cast<float2*>(op);
                float2 v = *reinterpret_cast<float2*>(&acc[i][j]);
                float2 o;
                o.x = fmaxf(v.x + prev.x, 0.0f);
                o.y = fmaxf(v.y + prev.y, 0.0f);
                *reinterpret_cast<float2*>(op) = o;
            }
        }
    }
}

// ---------------------------------------------------------------------------
// Launch: fork-join so GEMM1 (x@W_r+b) overlaps the scatter.
// ---------------------------------------------------------------------------
extern "C" void kernel_launch(void* const* d_in, const int* in_sizes, int n_in,
                              void* d_out, int out_size) {
    const float* x        = (const float*)d_in[0];
    const int*   edge_row = (const int*)d_in[1];
    const int*   edge_col = (const int*)d_in[2];
    const float* Wl       = (const float*)d_in[3];
    const float* bl       = (const float*)d_in[4];
    const float* Wr       = (const float*)d_in[5];
    float*       out      = (float*)d_out;

    int E = in_sizes[1];

    static cudaStream_t s1 = nullptr;
    static cudaEvent_t ev_root = nullptr, ev_agg = nullptr;
    if (s1 == nullptr) {
        cudaStreamCreateWithFlags(&s1, cudaStreamNonBlocking);
        cudaEventCreateWithFlags(&ev_root, cudaEventDisableTiming);
        cudaEventCreateWithFlags(&ev_agg, cudaEventDisableTiming);
    }

    // Fork: aggregation branch on s1
    cudaEventRecord(ev_root, 0);
    cudaStreamWaitEvent(s1, ev_root, 0);
    {
        int total4 = NNODES * INC / 4;   // dominant term
        zero_scratch<<<(total4 + 255) / 256, 256, 0, s1>>>();
        long long threads = (long long)E * 32;
        int blocks = (int)((threads + 255) / 256);
        edge_scatter<<<blocks, 256, 0, s1>>>(x, edge_row, edge_col, E);
    }
    cudaEventRecord(ev_agg, s1);

    // Concurrent on default stream: GEMM1 (independent of aggregation)
    {
        int blocks = (NNODES + 127) / 128;
        gemm_xr<<<blocks, 256>>>(x, Wr, bl, out, NNODES);
    }

    // Join, then GEMM2
    cudaStreamWaitEvent(0, ev_agg, 0);
    {
        int blocks = (NNODES + 127) / 128;
        gemm_aggl<<<blocks, 256>>>(Wl, out, NNODES);
    }
}